// round 9
// baseline (speedup 1.0000x reference)
#include <cuda_runtime.h>
#include <cuda_bf16.h>
#include <math.h>
#include <stdint.h>

// ---------------------------------------------------------------------------
// Problem constants
// ---------------------------------------------------------------------------
#define BATCH    8
#define NPTS     4096
#define WIDTH    768
#define HEADS    12
#define LAYERS   8
#define N_LAT    256
#define D_HEAD   64
#define IN_DIM   54
#define BN_ROWS  (BATCH * NPTS)        // 32768
#define LAT_ROWS (BATCH * N_LAT)       // 2048

#define FLAG_RES  1
#define FLAG_GELU 2

// ---------------------------------------------------------------------------
// Scratch (device globals; no allocation allowed)
// ---------------------------------------------------------------------------
__device__ float g_data[BN_ROWS * WIDTH];
__device__ float g_kv  [BN_ROWS * 2 * WIDTH];
__device__ float g_q   [N_LAT * WIDTH];
__device__ float g_attn[LAT_ROWS * WIDTH];
__device__ float g_x   [LAT_ROWS * WIDTH];
__device__ float g_h   [LAT_ROWS * WIDTH];
__device__ float g_ffn [LAT_ROWS * 4 * WIDTH];

// tf32-rounded weights, one big arena (contiguous regions)
#define W_CAQKV   0L
#define W_CAPROJ  1769472L
#define W_QKV     2359296L
#define W_PROJ    16515072L
#define W_FC      21233664L
#define W_FC2     40108032L
#define W_TOTAL   58982400L
__device__ float g_wtf[W_TOTAL];

// ---------------------------------------------------------------------------
// Helpers (sm_80+ features only — NO tcgen05; bench targets plain sm_103)
// ---------------------------------------------------------------------------
__device__ __forceinline__ uint32_t smem_u32(const void* p) {
    uint32_t a;
    asm("{ .reg .u64 t; cvta.to.shared.u64 t, %1; cvt.u32.u64 %0, t; }"
        : "=r"(a) : "l"(p));
    return a;
}
__device__ __forceinline__ void cp16(uint32_t dst, const void* src) {
    asm volatile("cp.async.cg.shared.global [%0], [%1], 16;"
                 :: "r"(dst), "l"(src) : "memory");
}
__device__ __forceinline__ float rna_f(float x) {
    uint32_t u;
    asm("cvt.rna.tf32.f32 %0, %1;" : "=r"(u) : "f"(x));
    return __uint_as_float(u);
}
__device__ __forceinline__ void mma1688(float* c, const uint32_t* a,
                                        uint32_t b0, uint32_t b1) {
    asm volatile(
        "mma.sync.aligned.m16n8k8.row.col.f32.tf32.tf32.f32 "
        "{%0,%1,%2,%3},{%4,%5,%6,%7},{%8,%9},{%0,%1,%2,%3};"
        : "+f"(c[0]), "+f"(c[1]), "+f"(c[2]), "+f"(c[3])
        : "r"(a[0]), "r"(a[1]), "r"(a[2]), "r"(a[3]), "r"(b0), "r"(b1));
}

// ---------------------------------------------------------------------------
// Fused rna tf32 rounding of ALL weights (single launch)
// dst arena is contiguous; 6 source regions. Units below are float4.
// ---------------------------------------------------------------------------
#define R4_E0 442368L
#define R4_E1 589824L
#define R4_E2 4128768L
#define R4_E3 5308416L
#define R4_E4 10027008L
#define R4_E5 14745600L

__global__ void rna_all(const float* __restrict__ s0, const float* __restrict__ s1,
                        const float* __restrict__ s2, const float* __restrict__ s3,
                        const float* __restrict__ s4, const float* __restrict__ s5,
                        float4* __restrict__ dst)
{
    long i = (long)blockIdx.x * 256 + threadIdx.x;
    if (i >= R4_E5) return;
    const float4* src; long off;
    if (i < R4_E0)      { src = (const float4*)s0; off = i; }
    else if (i < R4_E1) { src = (const float4*)s1; off = i - R4_E0; }
    else if (i < R4_E2) { src = (const float4*)s2; off = i - R4_E1; }
    else if (i < R4_E3) { src = (const float4*)s3; off = i - R4_E2; }
    else if (i < R4_E4) { src = (const float4*)s4; off = i - R4_E3; }
    else                { src = (const float4*)s5; off = i - R4_E4; }
    float4 v = src[off];
    v.x = rna_f(v.x); v.y = rna_f(v.y); v.z = rna_f(v.z); v.w = rna_f(v.w);
    dst[i] = v;
}

// ---------------------------------------------------------------------------
// tf32 mma.sync GEMM (unchanged from R8 — validated)
// ---------------------------------------------------------------------------
#define STRIDE 36
#define STAGE_BYTES (128 * STRIDE * 4)
#define GEMM_SMEM (4 * STAGE_BYTES)

__device__ __forceinline__ void load_stage(uint32_t abase, uint32_t bbase,
                                           const float* __restrict__ A,
                                           const float* __restrict__ B,
                                           int K, int cm, int cn, int kt, int tid)
{
    const float* Ak = A + (long)cm * K + kt * 32;
    const float* Bk = B + (long)cn * K + kt * 32;
    #pragma unroll
    for (int it = 0; it < 4; ++it) {
        int i = tid + it * 256;
        int r = i >> 3, c = i & 7;
        cp16(abase + r * (STRIDE * 4) + c * 16, Ak + (long)r * K + c * 4);
    }
    #pragma unroll
    for (int it = 0; it < 4; ++it) {
        int i = tid + it * 256;
        int r = i >> 3, c = i & 7;
        cp16(bbase + r * (STRIDE * 4) + c * 16, Bk + (long)r * K + c * 4);
    }
}

__global__ __launch_bounds__(256, 2)
void gemm_mma(const float* __restrict__ A, const float* __restrict__ Bw,
              const float* __restrict__ bias, const float* __restrict__ Res,
              float* __restrict__ C, int M, int N, int K, int flags)
{
    extern __shared__ char smem[];
    const uint32_t sb = smem_u32(smem);
    const uint32_t Au[2] = { sb, sb + STAGE_BYTES };
    const uint32_t Bu[2] = { sb + 2 * STAGE_BYTES, sb + 3 * STAGE_BYTES };
    const float* Af[2] = { (const float*)smem,
                           (const float*)(smem + STAGE_BYTES) };
    const float* Bf[2] = { (const float*)(smem + 2 * STAGE_BYTES),
                           (const float*)(smem + 3 * STAGE_BYTES) };

    const int tid = threadIdx.x;
    const int lane = tid & 31;
    const int wid = tid >> 5;
    const int warpM = wid & 3;
    const int warpN = wid >> 2;
    const int cm = blockIdx.y * 128;
    const int cn = blockIdx.x * 128;

    float acc[2][8][4];
    #pragma unroll
    for (int mi = 0; mi < 2; ++mi)
        #pragma unroll
        for (int ni = 0; ni < 8; ++ni)
            #pragma unroll
            for (int j = 0; j < 4; ++j) acc[mi][ni][j] = 0.f;

    const int KT = K >> 5;
    load_stage(Au[0], Bu[0], A, Bw, K, cm, cn, 0, tid);
    asm volatile("cp.async.commit_group;" ::: "memory");

    const int la = lane >> 2;
    const int lk = lane & 3;

    for (int kt = 0; kt < KT; ++kt) {
        const int cur = kt & 1;
        if (kt + 1 < KT) {
            load_stage(Au[cur ^ 1], Bu[cur ^ 1], A, Bw, K, cm, cn, kt + 1, tid);
            asm volatile("cp.async.commit_group;" ::: "memory");
            asm volatile("cp.async.wait_group 1;" ::: "memory");
        } else {
            asm volatile("cp.async.wait_group 0;" ::: "memory");
        }
        __syncthreads();

        const uint32_t* As = (const uint32_t*)Af[cur];
        const uint32_t* Bs = (const uint32_t*)Bf[cur];
        #pragma unroll
        for (int ks = 0; ks < 4; ++ks) {
            const int k0 = ks * 8 + lk;
            uint32_t a[2][4];
            #pragma unroll
            for (int mi = 0; mi < 2; ++mi) {
                const int r = warpM * 32 + mi * 16 + la;
                a[mi][0] = As[r * STRIDE + k0];
                a[mi][1] = As[(r + 8) * STRIDE + k0];
                a[mi][2] = As[r * STRIDE + k0 + 4];
                a[mi][3] = As[(r + 8) * STRIDE + k0 + 4];
            }
            #pragma unroll
            for (int ni = 0; ni < 8; ++ni) {
                const int n = warpN * 64 + ni * 8 + la;
                const uint32_t b0 = Bs[n * STRIDE + k0];
                const uint32_t b1 = Bs[n * STRIDE + k0 + 4];
                mma1688(acc[0][ni], a[0], b0, b1);
                mma1688(acc[1][ni], a[1], b0, b1);
            }
        }
        __syncthreads();
    }

    #pragma unroll
    for (int mi = 0; mi < 2; ++mi) {
        #pragma unroll
        for (int half = 0; half < 2; ++half) {
            const int row = cm + warpM * 32 + mi * 16 + la + half * 8;
            const long rb = (long)row * N;
            #pragma unroll
            for (int ni = 0; ni < 8; ++ni) {
                const int c = cn + warpN * 64 + ni * 8 + lk * 2;
                float v0 = acc[mi][ni][half * 2 + 0] + bias[c];
                float v1 = acc[mi][ni][half * 2 + 1] + bias[c + 1];
                if (flags & FLAG_GELU) {
                    v0 = 0.5f * v0 * (1.0f + erff(v0 * 0.70710678118654752f));
                    v1 = 0.5f * v1 * (1.0f + erff(v1 * 0.70710678118654752f));
                    v0 = rna_f(v0);
                    v1 = rna_f(v1);
                }
                if (flags & FLAG_RES) {
                    float2 r = *(const float2*)&Res[rb + c];
                    v0 += r.x; v1 += r.y;
                }
                float2 o; o.x = v0; o.y = v1;
                *(float2*)&C[rb + c] = o;
            }
        }
    }
}

// ---------------------------------------------------------------------------
// Fourier embed + input projection (rna output: feeds kv GEMM)
// ---------------------------------------------------------------------------
__global__ void embed_kernel(const float* __restrict__ pc,
                             const float* __restrict__ feats,
                             const float* __restrict__ inW,
                             const float* __restrict__ inb,
                             float* __restrict__ out)
{
    __shared__ float e[IN_DIM];
    const int row = blockIdx.x;
    const int t = threadIdx.x;
    if (t < IN_DIM) {
        float v;
        if (t < 3) {
            v = pc[row * 3 + t];
        } else if (t < 27) {
            int j = (t - 3) >> 3, f = (t - 3) & 7;
            v = sinf(pc[row * 3 + j] * (float)(1 << f));
        } else if (t < 51) {
            int j = (t - 27) >> 3, f = (t - 27) & 7;
            v = cosf(pc[row * 3 + j] * (float)(1 << f));
        } else {
            v = feats[row * 3 + (t - 51)];
        }
        e[t] = v;
    }
    __syncthreads();
    #pragma unroll
    for (int rep = 0; rep < 3; ++rep) {
        int o = t + rep * 256;
        const float* w = inW + o * IN_DIM;
        float s = inb[o];
        #pragma unroll
        for (int k = 0; k < IN_DIM; ++k) s = fmaf(w[k], e[k], s);
        out[(long)row * WIDTH + o] = rna_f(s);
    }
}

// ---------------------------------------------------------------------------
// LayerNorm (rna output: feeds qkv / fc GEMMs)
// ---------------------------------------------------------------------------
__global__ void ln_kernel(const float* __restrict__ X,
                          const float* __restrict__ s,
                          const float* __restrict__ b,
                          float* __restrict__ Y)
{
    const int row = blockIdx.x;
    const int t = threadIdx.x;
    const float* x = X + (long)row * WIDTH;
    float v0 = x[t], v1 = x[t + 256], v2 = x[t + 512];
    float sum = v0 + v1 + v2;
    float sq = v0 * v0 + v1 * v1 + v2 * v2;
    __shared__ float red[16];
    #pragma unroll
    for (int o = 16; o; o >>= 1) {
        sum += __shfl_xor_sync(0xffffffffu, sum, o);
        sq  += __shfl_xor_sync(0xffffffffu, sq,  o);
    }
    const int w = t >> 5, l = t & 31;
    if (l == 0) { red[w] = sum; red[w + 8] = sq; }
    __syncthreads();
    if (t < 32) {
        float a = (l < 8) ? red[l] : 0.f;
        float c = (l < 8) ? red[l + 8] : 0.f;
        #pragma unroll
        for (int o = 4; o; o >>= 1) {
            a += __shfl_xor_sync(0xffffffffu, a, o);
            c += __shfl_xor_sync(0xffffffffu, c, o);
        }
        if (l == 0) { red[0] = a; red[1] = c; }
    }
    __syncthreads();
    const float mu = red[0] * (1.f / WIDTH);
    const float var = red[1] * (1.f / WIDTH) - mu * mu;
    const float rs = rsqrtf(var + 1e-5f);
    float* y = Y + (long)row * WIDTH;
    y[t]       = rna_f((v0 - mu) * rs * s[t]       + b[t]);
    y[t + 256] = rna_f((v1 - mu) * rs * s[t + 256] + b[t + 256]);
    y[t + 512] = rna_f((v2 - mu) * rs * s[t + 512] + b[t + 512]);
}

// ---------------------------------------------------------------------------
// Flash attention via mma.sync tf32.
// 128 queries/CTA, 8 warps x 16 rows (warp-private softmax), 64-key chunks,
// double-buffered cp.async K/V, P round-trip through warp-private smem.
// Strides: Q/K/P = 68 floats, V = 72 floats (conflict-free fragments).
// ---------------------------------------------------------------------------
#define QST 68
#define KST 68
#define VST 72
#define PST 68
#define FK_P (128 * QST)
#define FK_K (FK_P + 128 * PST)
#define FK_V (FK_K + 2 * 64 * KST)
#define FLASH_SMEM ((FK_V + 2 * 64 * VST) * 4)   // 141312 bytes

__global__ __launch_bounds__(256, 1)
void flash_mma(const float* __restrict__ Qp, const float* __restrict__ Kp,
               const float* __restrict__ Vp, float* __restrict__ Op,
               int Lk, int qRS, int kRS, int oRS,
               long qBS, long kBS, long oBS,
               int qHS, int kHS, int oHS)
{
    extern __shared__ float sm[];
    const uint32_t sb = smem_u32(sm);
    float* Qs = sm;
    float* Ps = sm + FK_P;
    float* Ks = sm + FK_K;
    float* Vs = sm + FK_V;
    const uint32_t Ku[2] = { sb + FK_K * 4, sb + (FK_K + 64 * KST) * 4 };
    const uint32_t Vu[2] = { sb + FK_V * 4, sb + (FK_V + 64 * VST) * 4 };

    const int tid = threadIdx.x;
    const int lane = tid & 31, wid = tid >> 5;
    const int la = lane >> 2, lk = lane & 3;
    const int wbase = wid * 16;
    const int qt = blockIdx.x, h = blockIdx.y, b = blockIdx.z;

    const float* Q  = Qp + (long)b * qBS + h * qHS + (long)(qt * 128) * qRS;
    const float* Kb = Kp + (long)b * kBS + h * kHS;
    const float* Vb = Vp + (long)b * kBS + h * kHS;
    float*       O  = Op + (long)b * oBS + h * oHS + (long)(qt * 128) * oRS;

    // Q -> smem with rna (fragments are HW-truncated otherwise)
    for (int i = tid; i < 2048; i += 256) {
        int r = i >> 4, c4 = (i & 15) << 2;
        float4 v = *(const float4*)&Q[(long)r * qRS + c4];
        Qs[r * QST + c4 + 0] = rna_f(v.x);
        Qs[r * QST + c4 + 1] = rna_f(v.y);
        Qs[r * QST + c4 + 2] = rna_f(v.z);
        Qs[r * QST + c4 + 3] = rna_f(v.w);
    }

    // prologue: chunk 0 K/V
    #pragma unroll
    for (int it = 0; it < 4; ++it) {
        int i = tid + it * 256;
        int r = i >> 4, c4 = (i & 15) << 2;
        cp16(Ku[0] + (r * KST + c4) * 4, &Kb[(long)r * kRS + c4]);
        cp16(Vu[0] + (r * VST + c4) * 4, &Vb[(long)r * kRS + c4]);
    }
    asm volatile("cp.async.commit_group;" ::: "memory");

    float m0 = -1e30f, m1 = -1e30f, l0 = 0.f, l1 = 0.f;
    float o[8][4];
    #pragma unroll
    for (int ni = 0; ni < 8; ++ni)
        #pragma unroll
        for (int j = 0; j < 4; ++j) o[ni][j] = 0.f;

    const uint32_t* Qu = (const uint32_t*)Qs;
    const uint32_t* Pu = (const uint32_t*)Ps;
    const int NC = Lk >> 6;

    for (int c = 0; c < NC; ++c) {
        asm volatile("cp.async.wait_group 0;" ::: "memory");
        __syncthreads();    // chunk c visible; chunk c-1 reads fully retired

        if (c + 1 < NC) {
            const int buf = (c + 1) & 1;
            const long r0 = (long)(c + 1) * 64;
            #pragma unroll
            for (int it = 0; it < 4; ++it) {
                int i = tid + it * 256;
                int r = i >> 4, c4 = (i & 15) << 2;
                cp16(Ku[buf] + (r * KST + c4) * 4, &Kb[(r0 + r) * kRS + c4]);
                cp16(Vu[buf] + (r * VST + c4) * 4, &Vb[(r0 + r) * kRS + c4]);
            }
            asm volatile("cp.async.commit_group;" ::: "memory");
        }

        const uint32_t* Kc = (const uint32_t*)(Ks + (c & 1) * 64 * KST);
        const uint32_t* Vc = (const uint32_t*)(Vs + (c & 1) * 64 * VST);

        // S = Q K^T
        float s[8][4];
        #pragma unroll
        for (int ni = 0; ni < 8; ++ni)
            #pragma unroll
            for (int j = 0; j < 4; ++j) s[ni][j] = 0.f;
        #pragma unroll
        for (int ks = 0; ks < 8; ++ks) {
            const int k0 = ks * 8 + lk;
            uint32_t a[4];
            a[0] = Qu[(wbase + la) * QST + k0];
            a[1] = Qu[(wbase + la + 8) * QST + k0];
            a[2] = Qu[(wbase + la) * QST + k0 + 4];
            a[3] = Qu[(wbase + la + 8) * QST + k0 + 4];
            #pragma unroll
            for (int ni = 0; ni < 8; ++ni) {
                const int n = ni * 8 + la;
                mma1688(s[ni], a, Kc[n * KST + k0], Kc[n * KST + k0 + 4]);
            }
        }

        // online softmax (rows la / la+8; reduce over lk via xor 1,2)
        float mx0 = -1e30f, mx1 = -1e30f;
        #pragma unroll
        for (int ni = 0; ni < 8; ++ni) {
            s[ni][0] *= 0.125f; s[ni][1] *= 0.125f;
            s[ni][2] *= 0.125f; s[ni][3] *= 0.125f;
            mx0 = fmaxf(mx0, fmaxf(s[ni][0], s[ni][1]));
            mx1 = fmaxf(mx1, fmaxf(s[ni][2], s[ni][3]));
        }
        mx0 = fmaxf(mx0, __shfl_xor_sync(0xffffffffu, mx0, 1));
        mx0 = fmaxf(mx0, __shfl_xor_sync(0xffffffffu, mx0, 2));
        mx1 = fmaxf(mx1, __shfl_xor_sync(0xffffffffu, mx1, 1));
        mx1 = fmaxf(mx1, __shfl_xor_sync(0xffffffffu, mx1, 2));
        const float mn0 = fmaxf(m0, mx0), mn1 = fmaxf(m1, mx1);
        const float corr0 = __expf(m0 - mn0), corr1 = __expf(m1 - mn1);
        m0 = mn0; m1 = mn1;
        float sum0 = 0.f, sum1 = 0.f;
        #pragma unroll
        for (int ni = 0; ni < 8; ++ni) {
            s[ni][0] = __expf(s[ni][0] - mn0);
            s[ni][1] = __expf(s[ni][1] - mn0);
            s[ni][2] = __expf(s[ni][2] - mn1);
            s[ni][3] = __expf(s[ni][3] - mn1);
            sum0 += s[ni][0] + s[ni][1];
            sum1 += s[ni][2] + s[ni][3];
        }
        sum0 += __shfl_xor_sync(0xffffffffu, sum0, 1);
        sum0 += __shfl_xor_sync(0xffffffffu, sum0, 2);
        sum1 += __shfl_xor_sync(0xffffffffu, sum1, 1);
        sum1 += __shfl_xor_sync(0xffffffffu, sum1, 2);
        l0 = l0 * corr0 + sum0;
        l1 = l1 * corr1 + sum1;

        #pragma unroll
        for (int ni = 0; ni < 8; ++ni) {
            o[ni][0] *= corr0; o[ni][1] *= corr0;
            o[ni][2] *= corr1; o[ni][3] *= corr1;
            const int c2 = ni * 8 + lk * 2;
            Ps[(wbase + la) * PST + c2]         = rna_f(s[ni][0]);
            Ps[(wbase + la) * PST + c2 + 1]     = rna_f(s[ni][1]);
            Ps[(wbase + la + 8) * PST + c2]     = rna_f(s[ni][2]);
            Ps[(wbase + la + 8) * PST + c2 + 1] = rna_f(s[ni][3]);
        }
        __syncwarp();   // P rows are warp-private: warp-level fence suffices

        // O += P V
        #pragma unroll
        for (int ks = 0; ks < 8; ++ks) {
            const int k0 = ks * 8 + lk;
            uint32_t a[4];
            a[0] = Pu[(wbase + la) * PST + k0];
            a[1] = Pu[(wbase + la + 8) * PST + k0];
            a[2] = Pu[(wbase + la) * PST + k0 + 4];
            a[3] = Pu[(wbase + la + 8) * PST + k0 + 4];
            #pragma unroll
            for (int ni = 0; ni < 8; ++ni) {
                const int n = ni * 8 + la;
                mma1688(o[ni], a, Vc[k0 * VST + n], Vc[(k0 + 4) * VST + n]);
            }
        }
    }

    const float inv0 = 1.f / l0, inv1 = 1.f / l1;
    #pragma unroll
    for (int ni = 0; ni < 8; ++ni) {
        const int c2 = ni * 8 + lk * 2;
        float2 w0, w1;
        w0.x = rna_f(o[ni][0] * inv0); w0.y = rna_f(o[ni][1] * inv0);
        w1.x = rna_f(o[ni][2] * inv1); w1.y = rna_f(o[ni][3] * inv1);
        *(float2*)&O[(long)(wbase + la) * oRS + c2] = w0;
        *(float2*)&O[(long)(wbase + la + 8) * oRS + c2] = w1;
    }
}

__global__ void copy_kernel(const float* __restrict__ src, float* __restrict__ dst, int n)
{
    int i = blockIdx.x * 256 + threadIdx.x;
    if (i < n) dst[i] = src[i];
}

// ---------------------------------------------------------------------------
// kernel_launch
// ---------------------------------------------------------------------------
extern "C" void kernel_launch(void* const* d_in, const int* in_sizes, int n_in,
                              void* d_out, int out_size)
{
    const float* pc       = (const float*)d_in[0];
    const float* feats    = (const float*)d_in[1];
    const float* query    = (const float*)d_in[2];
    const float* in_W     = (const float*)d_in[3];
    const float* in_b     = (const float*)d_in[4];
    const float* ca_qkv_W = (const float*)d_in[5];
    const float* ca_qkv_b = (const float*)d_in[6];
    const float* ca_proj_W= (const float*)d_in[7];
    const float* ca_proj_b= (const float*)d_in[8];
    const float* ln1_s    = (const float*)d_in[9];
    const float* ln1_b    = (const float*)d_in[10];
    const float* qkv_W    = (const float*)d_in[11];
    const float* qkv_b    = (const float*)d_in[12];
    const float* proj_W   = (const float*)d_in[13];
    const float* proj_b   = (const float*)d_in[14];
    const float* ln2_s    = (const float*)d_in[15];
    const float* ln2_b    = (const float*)d_in[16];
    const float* fc_W     = (const float*)d_in[17];
    const float* fc_b     = (const float*)d_in[18];
    const float* fc2_W    = (const float*)d_in[19];
    const float* fc2_b    = (const float*)d_in[20];

    float *data, *kv, *qb, *attn, *x, *h, *ffn, *wtf;
    cudaGetSymbolAddress((void**)&data, g_data);
    cudaGetSymbolAddress((void**)&kv,   g_kv);
    cudaGetSymbolAddress((void**)&qb,   g_q);
    cudaGetSymbolAddress((void**)&attn, g_attn);
    cudaGetSymbolAddress((void**)&x,    g_x);
    cudaGetSymbolAddress((void**)&h,    g_h);
    cudaGetSymbolAddress((void**)&ffn,  g_ffn);
    cudaGetSymbolAddress((void**)&wtf,  g_wtf);

    cudaFuncSetAttribute(flash_mma, cudaFuncAttributeMaxDynamicSharedMemorySize,
                         FLASH_SMEM);
    cudaFuncSetAttribute(gemm_mma, cudaFuncAttributeMaxDynamicSharedMemorySize,
                         GEMM_SMEM);

    // 0) round all weights to tf32 (single fused launch)
    rna_all<<<(int)((R4_E5 + 255) / 256), 256>>>(
        ca_qkv_W, ca_proj_W, qkv_W, proj_W, fc_W, fc2_W, (float4*)wtf);

    // 1) fourier embed + input projection
    embed_kernel<<<BN_ROWS, 256>>>(pc, feats, in_W, in_b, data);

    // 2) kv = data @ ca_qkv_W[768:2304].T + b[768:]
    gemm_mma<<<dim3((2 * WIDTH) / 128, BN_ROWS / 128), 256, GEMM_SMEM>>>(
        data, wtf + W_CAQKV + (long)WIDTH * WIDTH, ca_qkv_b + WIDTH, nullptr, kv,
        BN_ROWS, 2 * WIDTH, WIDTH, 0);

    // 3) q = query @ ca_qkv_W[:768].T + b[:768]
    gemm_mma<<<dim3(WIDTH / 128, N_LAT / 128), 256, GEMM_SMEM>>>(
        query, wtf + W_CAQKV, ca_qkv_b, nullptr, qb, N_LAT, WIDTH, WIDTH, 0);

    // 4) cross attention (latents attend to 4096 points)
    flash_mma<<<dim3(N_LAT / 128, HEADS, BATCH), 256, FLASH_SMEM>>>(
        qb, kv, kv + WIDTH, attn,
        NPTS, WIDTH, 2 * WIDTH, WIDTH,
        0L, (long)NPTS * 2 * WIDTH, (long)N_LAT * WIDTH,
        D_HEAD, D_HEAD, D_HEAD);

    // 5) latents = attn @ ca_proj_W.T + b   (<- ncu -s 5 target)
    gemm_mma<<<dim3(WIDTH / 128, LAT_ROWS / 128), 256, GEMM_SMEM>>>(
        attn, wtf + W_CAPROJ, ca_proj_b, nullptr, x, LAT_ROWS, WIDTH, WIDTH, 0);

    // 6) transformer blocks
    for (int L = 0; L < LAYERS; ++L) {
        ln_kernel<<<LAT_ROWS, 256>>>(x, ln1_s + L * WIDTH, ln1_b + L * WIDTH, h);

        float* qkvb = ffn;
        gemm_mma<<<dim3((3 * WIDTH) / 128, LAT_ROWS / 128), 256, GEMM_SMEM>>>(
            h, wtf + W_QKV + (long)L * 3 * WIDTH * WIDTH, qkv_b + (long)L * 3 * WIDTH,
            nullptr, qkvb, LAT_ROWS, 3 * WIDTH, WIDTH, 0);

        flash_mma<<<dim3(N_LAT / 128, HEADS, BATCH), 256, FLASH_SMEM>>>(
            qkvb, qkvb + D_HEAD, qkvb + 2 * D_HEAD, attn,
            N_LAT, 3 * WIDTH, 3 * WIDTH, WIDTH,
            (long)N_LAT * 3 * WIDTH, (long)N_LAT * 3 * WIDTH, (long)N_LAT * WIDTH,
            3 * D_HEAD, 3 * D_HEAD, D_HEAD);

        gemm_mma<<<dim3(WIDTH / 128, LAT_ROWS / 128), 256, GEMM_SMEM>>>(
            attn, wtf + W_PROJ + (long)L * WIDTH * WIDTH, proj_b + (long)L * WIDTH,
            x, x, LAT_ROWS, WIDTH, WIDTH, FLAG_RES);

        ln_kernel<<<LAT_ROWS, 256>>>(x, ln2_s + L * WIDTH, ln2_b + L * WIDTH, h);

        gemm_mma<<<dim3((4 * WIDTH) / 128, LAT_ROWS / 128), 256, GEMM_SMEM>>>(
            h, wtf + W_FC + (long)L * 4 * WIDTH * WIDTH, fc_b + (long)L * 4 * WIDTH,
            nullptr, ffn, LAT_ROWS, 4 * WIDTH, WIDTH, FLAG_GELU);

        float* Cout = (L == LAYERS - 1) ? (float*)d_out : x;
        gemm_mma<<<dim3(WIDTH / 128, LAT_ROWS / 128), 256, GEMM_SMEM>>>(
            ffn, wtf + W_FC2 + (long)L * WIDTH * 4 * WIDTH, fc2_b + (long)L * WIDTH,
            x, Cout, LAT_ROWS, WIDTH, 4 * WIDTH, FLAG_RES);
    }

    // 7) pc passthrough if output holds both
    const int lat_elems = LAT_ROWS * WIDTH;
    const int pc_elems = BATCH * NPTS * 3;
    if (out_size >= lat_elems + pc_elems) {
        copy_kernel<<<(pc_elems + 255) / 256, 256>>>(
            pc, (float*)d_out + lat_elems, pc_elems);
    }
}

// round 10
// speedup vs baseline: 1.2757x; 1.2757x over previous
#include <cuda_runtime.h>
#include <cuda_bf16.h>
#include <math.h>
#include <stdint.h>

// ---------------------------------------------------------------------------
// Problem constants
// ---------------------------------------------------------------------------
#define BATCH    8
#define NPTS     4096
#define WIDTH    768
#define HEADS    12
#define LAYERS   8
#define N_LAT    256
#define D_HEAD   64
#define IN_DIM   54
#define BN_ROWS  (BATCH * NPTS)        // 32768
#define LAT_ROWS (BATCH * N_LAT)       // 2048

#define FLAG_RES  1
#define FLAG_GELU 2

// ---------------------------------------------------------------------------
// Scratch (device globals; no allocation allowed)
// ---------------------------------------------------------------------------
__device__ float g_data[BN_ROWS * WIDTH];
__device__ float g_kv  [BN_ROWS * 2 * WIDTH];
__device__ float g_q   [N_LAT * WIDTH];
__device__ float g_attn[LAT_ROWS * WIDTH];
__device__ float g_x   [LAT_ROWS * WIDTH];
__device__ float g_h   [LAT_ROWS * WIDTH];
__device__ float g_ffn [LAT_ROWS * 4 * WIDTH];

// tf32-rounded weights, one big arena (contiguous regions)
#define W_CAQKV   0L
#define W_CAPROJ  1769472L
#define W_QKV     2359296L
#define W_PROJ    16515072L
#define W_FC      21233664L
#define W_FC2     40108032L
#define W_TOTAL   58982400L
__device__ float g_wtf[W_TOTAL];

// ---------------------------------------------------------------------------
// Helpers (sm_80+ features only — NO tcgen05; bench targets plain sm_103)
// ---------------------------------------------------------------------------
__device__ __forceinline__ uint32_t smem_u32(const void* p) {
    uint32_t a;
    asm("{ .reg .u64 t; cvta.to.shared.u64 t, %1; cvt.u32.u64 %0, t; }"
        : "=r"(a) : "l"(p));
    return a;
}
__device__ __forceinline__ void cp16(uint32_t dst, const void* src) {
    asm volatile("cp.async.cg.shared.global [%0], [%1], 16;"
                 :: "r"(dst), "l"(src) : "memory");
}
__device__ __forceinline__ float rna_f(float x) {
    uint32_t u;
    asm("cvt.rna.tf32.f32 %0, %1;" : "=r"(u) : "f"(x));
    return __uint_as_float(u);
}
__device__ __forceinline__ void mma1688(float* c, const uint32_t* a,
                                        uint32_t b0, uint32_t b1) {
    asm volatile(
        "mma.sync.aligned.m16n8k8.row.col.f32.tf32.tf32.f32 "
        "{%0,%1,%2,%3},{%4,%5,%6,%7},{%8,%9},{%0,%1,%2,%3};"
        : "+f"(c[0]), "+f"(c[1]), "+f"(c[2]), "+f"(c[3])
        : "r"(a[0]), "r"(a[1]), "r"(a[2]), "r"(a[3]), "r"(b0), "r"(b1));
}

// ---------------------------------------------------------------------------
// Fused rna tf32 rounding of ALL weights (single launch); units are float4
// ---------------------------------------------------------------------------
#define R4_E0 442368L
#define R4_E1 589824L
#define R4_E2 4128768L
#define R4_E3 5308416L
#define R4_E4 10027008L
#define R4_E5 14745600L

__global__ void rna_all(const float* __restrict__ s0, const float* __restrict__ s1,
                        const float* __restrict__ s2, const float* __restrict__ s3,
                        const float* __restrict__ s4, const float* __restrict__ s5,
                        float4* __restrict__ dst)
{
    long i = (long)blockIdx.x * 256 + threadIdx.x;
    if (i >= R4_E5) return;
    const float4* src; long off;
    if (i < R4_E0)      { src = (const float4*)s0; off = i; }
    else if (i < R4_E1) { src = (const float4*)s1; off = i - R4_E0; }
    else if (i < R4_E2) { src = (const float4*)s2; off = i - R4_E1; }
    else if (i < R4_E3) { src = (const float4*)s3; off = i - R4_E2; }
    else if (i < R4_E4) { src = (const float4*)s4; off = i - R4_E3; }
    else                { src = (const float4*)s5; off = i - R4_E4; }
    float4 v = src[off];
    v.x = rna_f(v.x); v.y = rna_f(v.y); v.z = rna_f(v.z); v.w = rna_f(v.w);
    dst[i] = v;
}

// ---------------------------------------------------------------------------
// tf32 mma.sync GEMM: C[M,N] = A[M,K] @ B[N,K]^T + bias (+res)(gelu+rna)
// CTA tile 128x128, BK=32, double-buffered cp.async.
// 4 warps, each a 64x64 warp tile -> 1.0 LDS.32 per MMA (was 1.5).
// Requires M%128==0, N%128==0, K%32==0, 16B-aligned pointers.
// ---------------------------------------------------------------------------
#define STRIDE 36
#define STAGE_BYTES (128 * STRIDE * 4)
#define GEMM_SMEM (4 * STAGE_BYTES)

__device__ __forceinline__ void load_stage(uint32_t abase, uint32_t bbase,
                                           const float* __restrict__ A,
                                           const float* __restrict__ B,
                                           int K, int cm, int cn, int kt, int tid)
{
    const float* Ak = A + (long)cm * K + kt * 32;
    const float* Bk = B + (long)cn * K + kt * 32;
    #pragma unroll
    for (int it = 0; it < 8; ++it) {
        int i = tid + it * 128;
        int r = i >> 3, c = i & 7;
        cp16(abase + r * (STRIDE * 4) + c * 16, Ak + (long)r * K + c * 4);
    }
    #pragma unroll
    for (int it = 0; it < 8; ++it) {
        int i = tid + it * 128;
        int r = i >> 3, c = i & 7;
        cp16(bbase + r * (STRIDE * 4) + c * 16, Bk + (long)r * K + c * 4);
    }
}

__global__ __launch_bounds__(128, 2)
void gemm_mma(const float* __restrict__ A, const float* __restrict__ Bw,
              const float* __restrict__ bias, const float* __restrict__ Res,
              float* __restrict__ C, int M, int N, int K, int flags)
{
    extern __shared__ char smem[];
    const uint32_t sb = smem_u32(smem);
    const uint32_t Au[2] = { sb, sb + STAGE_BYTES };
    const uint32_t Bu[2] = { sb + 2 * STAGE_BYTES, sb + 3 * STAGE_BYTES };
    const float* Af[2] = { (const float*)smem,
                           (const float*)(smem + STAGE_BYTES) };
    const float* Bf[2] = { (const float*)(smem + 2 * STAGE_BYTES),
                           (const float*)(smem + 3 * STAGE_BYTES) };

    const int tid = threadIdx.x;
    const int lane = tid & 31;
    const int wid = tid >> 5;        // 0..3
    const int warpM = wid & 1;       // 2 warps along M (64 rows each)
    const int warpN = wid >> 1;      // 2 warps along N (64 cols each)
    const int cm = blockIdx.y * 128;
    const int cn = blockIdx.x * 128;

    float acc[4][8][4];
    #pragma unroll
    for (int mi = 0; mi < 4; ++mi)
        #pragma unroll
        for (int ni = 0; ni < 8; ++ni)
            #pragma unroll
            for (int j = 0; j < 4; ++j) acc[mi][ni][j] = 0.f;

    const int KT = K >> 5;
    load_stage(Au[0], Bu[0], A, Bw, K, cm, cn, 0, tid);
    asm volatile("cp.async.commit_group;" ::: "memory");

    const int la = lane >> 2;
    const int lk = lane & 3;

    for (int kt = 0; kt < KT; ++kt) {
        const int cur = kt & 1;
        if (kt + 1 < KT) {
            load_stage(Au[cur ^ 1], Bu[cur ^ 1], A, Bw, K, cm, cn, kt + 1, tid);
            asm volatile("cp.async.commit_group;" ::: "memory");
            asm volatile("cp.async.wait_group 1;" ::: "memory");
        } else {
            asm volatile("cp.async.wait_group 0;" ::: "memory");
        }
        __syncthreads();

        const uint32_t* As = (const uint32_t*)Af[cur];
        const uint32_t* Bs = (const uint32_t*)Bf[cur];
        #pragma unroll
        for (int ks = 0; ks < 4; ++ks) {
            const int k0 = ks * 8 + lk;
            uint32_t a[4][4];
            #pragma unroll
            for (int mi = 0; mi < 4; ++mi) {
                const int r = warpM * 64 + mi * 16 + la;
                a[mi][0] = As[r * STRIDE + k0];
                a[mi][1] = As[(r + 8) * STRIDE + k0];
                a[mi][2] = As[r * STRIDE + k0 + 4];
                a[mi][3] = As[(r + 8) * STRIDE + k0 + 4];
            }
            #pragma unroll
            for (int ni = 0; ni < 8; ++ni) {
                const int n = warpN * 64 + ni * 8 + la;
                const uint32_t b0 = Bs[n * STRIDE + k0];
                const uint32_t b1 = Bs[n * STRIDE + k0 + 4];
                #pragma unroll
                for (int mi = 0; mi < 4; ++mi)
                    mma1688(acc[mi][ni], a[mi], b0, b1);
            }
        }
        __syncthreads();
    }

    // epilogue from register accumulators
    #pragma unroll
    for (int mi = 0; mi < 4; ++mi) {
        #pragma unroll
        for (int half = 0; half < 2; ++half) {
            const int row = cm + warpM * 64 + mi * 16 + la + half * 8;
            const long rb = (long)row * N;
            #pragma unroll
            for (int ni = 0; ni < 8; ++ni) {
                const int c = cn + warpN * 64 + ni * 8 + lk * 2;
                float v0 = acc[mi][ni][half * 2 + 0] + bias[c];
                float v1 = acc[mi][ni][half * 2 + 1] + bias[c + 1];
                if (flags & FLAG_GELU) {
                    v0 = 0.5f * v0 * (1.0f + erff(v0 * 0.70710678118654752f));
                    v1 = 0.5f * v1 * (1.0f + erff(v1 * 0.70710678118654752f));
                    v0 = rna_f(v0);
                    v1 = rna_f(v1);
                }
                if (flags & FLAG_RES) {
                    float2 r = *(const float2*)&Res[rb + c];
                    v0 += r.x; v1 += r.y;
                }
                float2 o; o.x = v0; o.y = v1;
                *(float2*)&C[rb + c] = o;
            }
        }
    }
}

// ---------------------------------------------------------------------------
// Fourier embed + input projection (rna output: feeds kv GEMM)
// ---------------------------------------------------------------------------
__global__ void embed_kernel(const float* __restrict__ pc,
                             const float* __restrict__ feats,
                             const float* __restrict__ inW,
                             const float* __restrict__ inb,
                             float* __restrict__ out)
{
    __shared__ float e[IN_DIM];
    const int row = blockIdx.x;
    const int t = threadIdx.x;
    if (t < IN_DIM) {
        float v;
        if (t < 3) {
            v = pc[row * 3 + t];
        } else if (t < 27) {
            int j = (t - 3) >> 3, f = (t - 3) & 7;
            v = sinf(pc[row * 3 + j] * (float)(1 << f));
        } else if (t < 51) {
            int j = (t - 27) >> 3, f = (t - 27) & 7;
            v = cosf(pc[row * 3 + j] * (float)(1 << f));
        } else {
            v = feats[row * 3 + (t - 51)];
        }
        e[t] = v;
    }
    __syncthreads();
    #pragma unroll
    for (int rep = 0; rep < 3; ++rep) {
        int o = t + rep * 256;
        const float* w = inW + o * IN_DIM;
        float s = inb[o];
        #pragma unroll
        for (int k = 0; k < IN_DIM; ++k) s = fmaf(w[k], e[k], s);
        out[(long)row * WIDTH + o] = rna_f(s);
    }
}

// ---------------------------------------------------------------------------
// LayerNorm (rna output: feeds qkv / fc GEMMs)
// ---------------------------------------------------------------------------
__global__ void ln_kernel(const float* __restrict__ X,
                          const float* __restrict__ s,
                          const float* __restrict__ b,
                          float* __restrict__ Y)
{
    const int row = blockIdx.x;
    const int t = threadIdx.x;
    const float* x = X + (long)row * WIDTH;
    float v0 = x[t], v1 = x[t + 256], v2 = x[t + 512];
    float sum = v0 + v1 + v2;
    float sq = v0 * v0 + v1 * v1 + v2 * v2;
    __shared__ float red[16];
    #pragma unroll
    for (int o = 16; o; o >>= 1) {
        sum += __shfl_xor_sync(0xffffffffu, sum, o);
        sq  += __shfl_xor_sync(0xffffffffu, sq,  o);
    }
    const int w = t >> 5, l = t & 31;
    if (l == 0) { red[w] = sum; red[w + 8] = sq; }
    __syncthreads();
    if (t < 32) {
        float a = (l < 8) ? red[l] : 0.f;
        float c = (l < 8) ? red[l + 8] : 0.f;
        #pragma unroll
        for (int o = 4; o; o >>= 1) {
            a += __shfl_xor_sync(0xffffffffu, a, o);
            c += __shfl_xor_sync(0xffffffffu, c, o);
        }
        if (l == 0) { red[0] = a; red[1] = c; }
    }
    __syncthreads();
    const float mu = red[0] * (1.f / WIDTH);
    const float var = red[1] * (1.f / WIDTH) - mu * mu;
    const float rs = rsqrtf(var + 1e-5f);
    float* y = Y + (long)row * WIDTH;
    y[t]       = rna_f((v0 - mu) * rs * s[t]       + b[t]);
    y[t + 256] = rna_f((v1 - mu) * rs * s[t + 256] + b[t + 256]);
    y[t + 512] = rna_f((v2 - mu) * rs * s[t + 512] + b[t + 512]);
}

// ---------------------------------------------------------------------------
// Flash attention fp32 SIMT (R8 version — known good; rna output)
// ---------------------------------------------------------------------------
#define FLASH_SMEM ((2 * 128 * 65 + 2 * 64 * 65) * 4)

__global__ __launch_bounds__(256)
void flash_kernel(const float* __restrict__ Qp, const float* __restrict__ Kp,
                  const float* __restrict__ Vp, float* __restrict__ Op,
                  int Lk, int qRS, int kRS, int oRS,
                  long qBS, long kBS, long oBS,
                  int qHS, int kHS, int oHS)
{
    extern __shared__ float sm[];
    float* Qs = sm;
    float* Ps = sm + 128 * 65;
    float* Ks = sm + 2 * 128 * 65;
    float* Vs = Ks + 64 * 65;

    const int tid = threadIdx.x;
    const int tx = tid & 15;
    const int ty = tid >> 4;
    const int qt = blockIdx.x, h = blockIdx.y, b = blockIdx.z;

    const float* Q  = Qp + (long)b * qBS + h * qHS + (long)(qt * 128) * qRS;
    const float* Kb = Kp + (long)b * kBS + h * kHS;
    const float* Vb = Vp + (long)b * kBS + h * kHS;
    float*       O  = Op + (long)b * oBS + h * oHS + (long)(qt * 128) * oRS;

    for (int idx = tid; idx < 128 * 64; idx += 256) {
        int r = idx >> 6, d = idx & 63;
        Qs[r * 65 + d] = Q[(long)r * qRS + d];
    }

    float m[8], l[8], o[8][4];
    #pragma unroll
    for (int i = 0; i < 8; ++i) {
        m[i] = -3.0e38f; l[i] = 0.f;
        #pragma unroll
        for (int j = 0; j < 4; ++j) o[i][j] = 0.f;
    }
    __syncthreads();

    for (int c0 = 0; c0 < Lk; c0 += 64) {
        for (int idx = tid; idx < 64 * 64; idx += 256) {
            int r = idx >> 6, d = idx & 63;
            Ks[r * 65 + d] = Kb[(long)(c0 + r) * kRS + d];
            Vs[r * 65 + d] = Vb[(long)(c0 + r) * kRS + d];
        }
        __syncthreads();

        float s[8][4];
        #pragma unroll
        for (int i = 0; i < 8; ++i)
            #pragma unroll
            for (int j = 0; j < 4; ++j) s[i][j] = 0.f;
        #pragma unroll 16
        for (int d = 0; d < 64; ++d) {
            float a[8], bf[4];
            #pragma unroll
            for (int i = 0; i < 8; ++i) a[i] = Qs[(ty * 8 + i) * 65 + d];
            #pragma unroll
            for (int j = 0; j < 4; ++j) bf[j] = Ks[(tx * 4 + j) * 65 + d];
            #pragma unroll
            for (int i = 0; i < 8; ++i)
                #pragma unroll
                for (int j = 0; j < 4; ++j)
                    s[i][j] = fmaf(a[i], bf[j], s[i][j]);
        }

        #pragma unroll
        for (int i = 0; i < 8; ++i) {
            #pragma unroll
            for (int j = 0; j < 4; ++j) s[i][j] *= 0.125f;
            float mx = fmaxf(fmaxf(s[i][0], s[i][1]), fmaxf(s[i][2], s[i][3]));
            #pragma unroll
            for (int off = 1; off < 16; off <<= 1)
                mx = fmaxf(mx, __shfl_xor_sync(0xffffffffu, mx, off));
            const float mnew = fmaxf(m[i], mx);
            const float corr = __expf(m[i] - mnew);
            m[i] = mnew;
            float rsum = 0.f;
            #pragma unroll
            for (int j = 0; j < 4; ++j) {
                s[i][j] = __expf(s[i][j] - mnew);
                rsum += s[i][j];
            }
            #pragma unroll
            for (int off = 1; off < 16; off <<= 1)
                rsum += __shfl_xor_sync(0xffffffffu, rsum, off);
            l[i] = l[i] * corr + rsum;
            #pragma unroll
            for (int j = 0; j < 4; ++j) {
                o[i][j] *= corr;
                Ps[(ty * 8 + i) * 65 + tx * 4 + j] = s[i][j];
            }
        }
        __syncthreads();

        #pragma unroll 16
        for (int c = 0; c < 64; ++c) {
            float a[8], bf[4];
            #pragma unroll
            for (int i = 0; i < 8; ++i) a[i] = Ps[(ty * 8 + i) * 65 + c];
            #pragma unroll
            for (int j = 0; j < 4; ++j) bf[j] = Vs[c * 65 + tx * 4 + j];
            #pragma unroll
            for (int i = 0; i < 8; ++i)
                #pragma unroll
                for (int j = 0; j < 4; ++j)
                    o[i][j] = fmaf(a[i], bf[j], o[i][j]);
        }
        __syncthreads();
    }

    #pragma unroll
    for (int i = 0; i < 8; ++i) {
        const float inv = 1.f / l[i];
        const int r = ty * 8 + i;
        #pragma unroll
        for (int j = 0; j < 4; ++j)
            O[(long)r * oRS + tx * 4 + j] = rna_f(o[i][j] * inv);
    }
}

__global__ void copy_kernel(const float* __restrict__ src, float* __restrict__ dst, int n)
{
    int i = blockIdx.x * 256 + threadIdx.x;
    if (i < n) dst[i] = src[i];
}

// ---------------------------------------------------------------------------
// kernel_launch
// ---------------------------------------------------------------------------
extern "C" void kernel_launch(void* const* d_in, const int* in_sizes, int n_in,
                              void* d_out, int out_size)
{
    const float* pc       = (const float*)d_in[0];
    const float* feats    = (const float*)d_in[1];
    const float* query    = (const float*)d_in[2];
    const float* in_W     = (const float*)d_in[3];
    const float* in_b     = (const float*)d_in[4];
    const float* ca_qkv_W = (const float*)d_in[5];
    const float* ca_qkv_b = (const float*)d_in[6];
    const float* ca_proj_W= (const float*)d_in[7];
    const float* ca_proj_b= (const float*)d_in[8];
    const float* ln1_s    = (const float*)d_in[9];
    const float* ln1_b    = (const float*)d_in[10];
    const float* qkv_W    = (const float*)d_in[11];
    const float* qkv_b    = (const float*)d_in[12];
    const float* proj_W   = (const float*)d_in[13];
    const float* proj_b   = (const float*)d_in[14];
    const float* ln2_s    = (const float*)d_in[15];
    const float* ln2_b    = (const float*)d_in[16];
    const float* fc_W     = (const float*)d_in[17];
    const float* fc_b     = (const float*)d_in[18];
    const float* fc2_W    = (const float*)d_in[19];
    const float* fc2_b    = (const float*)d_in[20];

    float *data, *kv, *qb, *attn, *x, *h, *ffn, *wtf;
    cudaGetSymbolAddress((void**)&data, g_data);
    cudaGetSymbolAddress((void**)&kv,   g_kv);
    cudaGetSymbolAddress((void**)&qb,   g_q);
    cudaGetSymbolAddress((void**)&attn, g_attn);
    cudaGetSymbolAddress((void**)&x,    g_x);
    cudaGetSymbolAddress((void**)&h,    g_h);
    cudaGetSymbolAddress((void**)&ffn,  g_ffn);
    cudaGetSymbolAddress((void**)&wtf,  g_wtf);

    cudaFuncSetAttribute(flash_kernel, cudaFuncAttributeMaxDynamicSharedMemorySize,
                         FLASH_SMEM);
    cudaFuncSetAttribute(gemm_mma, cudaFuncAttributeMaxDynamicSharedMemorySize,
                         GEMM_SMEM);

    // 0) round all weights to tf32 (single fused launch)
    rna_all<<<(int)((R4_E5 + 255) / 256), 256>>>(
        ca_qkv_W, ca_proj_W, qkv_W, proj_W, fc_W, fc2_W, (float4*)wtf);

    // 1) fourier embed + input projection
    embed_kernel<<<BN_ROWS, 256>>>(pc, feats, in_W, in_b, data);

    // 2) kv = data @ ca_qkv_W[768:2304].T + b[768:]
    gemm_mma<<<dim3((2 * WIDTH) / 128, BN_ROWS / 128), 128, GEMM_SMEM>>>(
        data, wtf + W_CAQKV + (long)WIDTH * WIDTH, ca_qkv_b + WIDTH, nullptr, kv,
        BN_ROWS, 2 * WIDTH, WIDTH, 0);

    // 3) q = query @ ca_qkv_W[:768].T + b[:768]
    gemm_mma<<<dim3(WIDTH / 128, N_LAT / 128), 128, GEMM_SMEM>>>(
        query, wtf + W_CAQKV, ca_qkv_b, nullptr, qb, N_LAT, WIDTH, WIDTH, 0);

    // 4) cross attention (latents attend to 4096 points)
    flash_kernel<<<dim3(N_LAT / 128, HEADS, BATCH), 256, FLASH_SMEM>>>(
        qb, kv, kv + WIDTH, attn,
        NPTS, WIDTH, 2 * WIDTH, WIDTH,
        0L, (long)NPTS * 2 * WIDTH, (long)N_LAT * WIDTH,
        D_HEAD, D_HEAD, D_HEAD);

    // 5) latents = attn @ ca_proj_W.T + b
    gemm_mma<<<dim3(WIDTH / 128, LAT_ROWS / 128), 128, GEMM_SMEM>>>(
        attn, wtf + W_CAPROJ, ca_proj_b, nullptr, x, LAT_ROWS, WIDTH, WIDTH, 0);

    // 6) transformer blocks
    for (int L = 0; L < LAYERS; ++L) {
        ln_kernel<<<LAT_ROWS, 256>>>(x, ln1_s + L * WIDTH, ln1_b + L * WIDTH, h);

        float* qkvb = ffn;
        gemm_mma<<<dim3((3 * WIDTH) / 128, LAT_ROWS / 128), 128, GEMM_SMEM>>>(
            h, wtf + W_QKV + (long)L * 3 * WIDTH * WIDTH, qkv_b + (long)L * 3 * WIDTH,
            nullptr, qkvb, LAT_ROWS, 3 * WIDTH, WIDTH, 0);

        flash_kernel<<<dim3(N_LAT / 128, HEADS, BATCH), 256, FLASH_SMEM>>>(
            qkvb, qkvb + D_HEAD, qkvb + 2 * D_HEAD, attn,
            N_LAT, 3 * WIDTH, 3 * WIDTH, WIDTH,
            (long)N_LAT * 3 * WIDTH, (long)N_LAT * 3 * WIDTH, (long)N_LAT * WIDTH,
            3 * D_HEAD, 3 * D_HEAD, D_HEAD);

        gemm_mma<<<dim3(WIDTH / 128, LAT_ROWS / 128), 128, GEMM_SMEM>>>(
            attn, wtf + W_PROJ + (long)L * WIDTH * WIDTH, proj_b + (long)L * WIDTH,
            x, x, LAT_ROWS, WIDTH, WIDTH, FLAG_RES);

        ln_kernel<<<LAT_ROWS, 256>>>(x, ln2_s + L * WIDTH, ln2_b + L * WIDTH, h);

        gemm_mma<<<dim3((4 * WIDTH) / 128, LAT_ROWS / 128), 128, GEMM_SMEM>>>(
            h, wtf + W_FC + (long)L * 4 * WIDTH * WIDTH, fc_b + (long)L * 4 * WIDTH,
            nullptr, ffn, LAT_ROWS, 4 * WIDTH, WIDTH, FLAG_GELU);

        float* Cout = (L == LAYERS - 1) ? (float*)d_out : x;
        gemm_mma<<<dim3(WIDTH / 128, LAT_ROWS / 128), 128, GEMM_SMEM>>>(
            ffn, wtf + W_FC2 + (long)L * WIDTH * 4 * WIDTH, fc2_b + (long)L * WIDTH,
            x, Cout, LAT_ROWS, WIDTH, 4 * WIDTH, FLAG_RES);
    }

    // 7) pc passthrough if output holds both
    const int lat_elems = LAT_ROWS * WIDTH;
    const int pc_elems = BATCH * NPTS * 3;
    if (out_size >= lat_elems + pc_elems) {
        copy_kernel<<<(pc_elems + 255) / 256, 256>>>(
            pc, (float*)d_out + lat_elems, pc_elems);
    }
}

// round 13
// speedup vs baseline: 1.3666x; 1.0713x over previous
#include <cuda_runtime.h>
#include <cuda_bf16.h>
#include <math.h>
#include <stdint.h>

// ---------------------------------------------------------------------------
// Problem constants
// ---------------------------------------------------------------------------
#define BATCH    8
#define NPTS     4096
#define WIDTH    768
#define HEADS    12
#define LAYERS   8
#define N_LAT    256
#define D_HEAD   64
#define IN_DIM   54
#define BN_ROWS  (BATCH * NPTS)        // 32768
#define LAT_ROWS (BATCH * N_LAT)       // 2048

#define FLAG_RES  1
#define FLAG_GELU 2

// ---------------------------------------------------------------------------
// Scratch (device globals; no allocation allowed)
// ---------------------------------------------------------------------------
__device__ float g_data[BN_ROWS * WIDTH];
__device__ float g_kv  [BN_ROWS * 2 * WIDTH];
__device__ float g_q   [N_LAT * WIDTH];
__device__ float g_attn[LAT_ROWS * WIDTH];
__device__ float g_x   [LAT_ROWS * WIDTH];
__device__ float g_h   [LAT_ROWS * WIDTH];
__device__ float g_ffn [LAT_ROWS * 4 * WIDTH];

// tf32-rounded weights, one big arena (contiguous regions)
#define W_CAQKV   0L
#define W_CAPROJ  1769472L
#define W_QKV     2359296L
#define W_PROJ    16515072L
#define W_FC      21233664L
#define W_FC2     40108032L
#define W_TOTAL   58982400L
__device__ float g_wtf[W_TOTAL];

// ---------------------------------------------------------------------------
// Helpers (sm_80+ features only — NO tcgen05; bench targets plain sm_103)
// ---------------------------------------------------------------------------
__device__ __forceinline__ uint32_t smem_u32(const void* p) {
    uint32_t a;
    asm("{ .reg .u64 t; cvta.to.shared.u64 t, %1; cvt.u32.u64 %0, t; }"
        : "=r"(a) : "l"(p));
    return a;
}
__device__ __forceinline__ void cp16(uint32_t dst, const void* src) {
    asm volatile("cp.async.cg.shared.global [%0], [%1], 16;"
                 :: "r"(dst), "l"(src) : "memory");
}
__device__ __forceinline__ float rna_f(float x) {
    uint32_t u;
    asm("cvt.rna.tf32.f32 %0, %1;" : "=r"(u) : "f"(x));
    return __uint_as_float(u);
}
__device__ __forceinline__ void mma1688(float* c, const uint32_t* a,
                                        uint32_t b0, uint32_t b1) {
    asm volatile(
        "mma.sync.aligned.m16n8k8.row.col.f32.tf32.tf32.f32 "
        "{%0,%1,%2,%3},{%4,%5,%6,%7},{%8,%9},{%0,%1,%2,%3};"
        : "+f"(c[0]), "+f"(c[1]), "+f"(c[2]), "+f"(c[3])
        : "r"(a[0]), "r"(a[1]), "r"(a[2]), "r"(a[3]), "r"(b0), "r"(b1));
}

// ---------------------------------------------------------------------------
// Fused rna tf32 rounding of ALL weights (single launch); units are float4
// ---------------------------------------------------------------------------
#define R4_E0 442368L
#define R4_E1 589824L
#define R4_E2 4128768L
#define R4_E3 5308416L
#define R4_E4 10027008L
#define R4_E5 14745600L

__global__ void rna_all(const float* __restrict__ s0, const float* __restrict__ s1,
                        const float* __restrict__ s2, const float* __restrict__ s3,
                        const float* __restrict__ s4, const float* __restrict__ s5,
                        float4* __restrict__ dst)
{
    long i = (long)blockIdx.x * 256 + threadIdx.x;
    if (i >= R4_E5) return;
    const float4* src; long off;
    if (i < R4_E0)      { src = (const float4*)s0; off = i; }
    else if (i < R4_E1) { src = (const float4*)s1; off = i - R4_E0; }
    else if (i < R4_E2) { src = (const float4*)s2; off = i - R4_E1; }
    else if (i < R4_E3) { src = (const float4*)s3; off = i - R4_E2; }
    else if (i < R4_E4) { src = (const float4*)s4; off = i - R4_E3; }
    else                { src = (const float4*)s5; off = i - R4_E4; }
    float4 v = src[off];
    v.x = rna_f(v.x); v.y = rna_f(v.y); v.z = rna_f(v.z); v.w = rna_f(v.w);
    dst[i] = v;
}

// ---------------------------------------------------------------------------
// tf32 mma.sync GEMM: C[M,N] = A[M,K] @ B[N,K]^T + bias (+res)(gelu+rna)
// CTA tile 128x128, BK=32, THREE-stage cp.async pipeline, ONE barrier/k-tile.
// 8 warps (R8 tiling: warp tile 32x64 -> 128 regs -> 2 CTA/SM = 16 warps/SM).
// Requires M%128==0, N%128==0, K%64==0, 16B-aligned pointers.
// ---------------------------------------------------------------------------
#define NSTG 3
#define STRIDE 36
#define STAGE_BYTES (128 * STRIDE * 4)           // 18432
#define GEMM_SMEM (2 * NSTG * STAGE_BYTES)       // 110592

__device__ __forceinline__ void load_stage(uint32_t abase, uint32_t bbase,
                                           const float* __restrict__ A,
                                           const float* __restrict__ B,
                                           int K, int cm, int cn, int kt, int tid)
{
    const float* Ak = A + (long)cm * K + kt * 32;
    const float* Bk = B + (long)cn * K + kt * 32;
    #pragma unroll
    for (int it = 0; it < 4; ++it) {
        int i = tid + it * 256;
        int r = i >> 3, c = i & 7;
        cp16(abase + r * (STRIDE * 4) + c * 16, Ak + (long)r * K + c * 4);
    }
    #pragma unroll
    for (int it = 0; it < 4; ++it) {
        int i = tid + it * 256;
        int r = i >> 3, c = i & 7;
        cp16(bbase + r * (STRIDE * 4) + c * 16, Bk + (long)r * K + c * 4);
    }
}

__global__ __launch_bounds__(256, 2)
void gemm_mma(const float* __restrict__ A, const float* __restrict__ Bw,
              const float* __restrict__ bias, const float* __restrict__ Res,
              float* __restrict__ C, int M, int N, int K, int flags)
{
    extern __shared__ char smem[];
    const uint32_t sb = smem_u32(smem);

    const int tid = threadIdx.x;
    const int lane = tid & 31;
    const int wid = tid >> 5;
    const int warpM = wid & 3;        // 4 warps along M (32 rows each)
    const int warpN = wid >> 2;       // 2 warps along N (64 cols each)
    const int cm = blockIdx.y * 128;
    const int cn = blockIdx.x * 128;

    float acc[2][8][4];
    #pragma unroll
    for (int mi = 0; mi < 2; ++mi)
        #pragma unroll
        for (int ni = 0; ni < 8; ++ni)
            #pragma unroll
            for (int j = 0; j < 4; ++j) acc[mi][ni][j] = 0.f;

    const int KT = K >> 5;
    // prologue: stages 0,1 in flight
    #pragma unroll
    for (int p = 0; p < NSTG - 1; ++p) {
        load_stage(sb + p * STAGE_BYTES, sb + (NSTG + p) * STAGE_BYTES,
                   A, Bw, K, cm, cn, p, tid);
        asm volatile("cp.async.commit_group;" ::: "memory");
    }

    const int la = lane >> 2;
    const int lk = lane & 3;

    for (int kt = 0; kt < KT; ++kt) {
        const int s = kt % NSTG;
        asm volatile("cp.async.wait_group 1;" ::: "memory");   // stage kt landed
        __syncthreads();   // also: all warps done reading stage (kt+2)%NSTG

        // prefetch kt+2 into the slot just freed
        {
            const int kn = kt + NSTG - 1;
            if (kn < KT) {
                const int sn = kn % NSTG;
                load_stage(sb + sn * STAGE_BYTES, sb + (NSTG + sn) * STAGE_BYTES,
                           A, Bw, K, cm, cn, kn, tid);
            }
            asm volatile("cp.async.commit_group;" ::: "memory");
        }

        const uint32_t* As = (const uint32_t*)(smem + s * STAGE_BYTES);
        const uint32_t* Bs = (const uint32_t*)(smem + (NSTG + s) * STAGE_BYTES);
        #pragma unroll
        for (int ks = 0; ks < 4; ++ks) {
            const int k0 = ks * 8 + lk;
            uint32_t a[2][4];
            #pragma unroll
            for (int mi = 0; mi < 2; ++mi) {
                const int r = warpM * 32 + mi * 16 + la;
                a[mi][0] = As[r * STRIDE + k0];
                a[mi][1] = As[(r + 8) * STRIDE + k0];
                a[mi][2] = As[r * STRIDE + k0 + 4];
                a[mi][3] = As[(r + 8) * STRIDE + k0 + 4];
            }
            #pragma unroll
            for (int ni = 0; ni < 8; ++ni) {
                const int n = warpN * 64 + ni * 8 + la;
                const uint32_t b0 = Bs[n * STRIDE + k0];
                const uint32_t b1 = Bs[n * STRIDE + k0 + 4];
                mma1688(acc[0][ni], a[0], b0, b1);
                mma1688(acc[1][ni], a[1], b0, b1);
            }
        }
    }

    // epilogue from register accumulators
    #pragma unroll
    for (int mi = 0; mi < 2; ++mi) {
        #pragma unroll
        for (int half = 0; half < 2; ++half) {
            const int row = cm + warpM * 32 + mi * 16 + la + half * 8;
            const long rb = (long)row * N;
            #pragma unroll
            for (int ni = 0; ni < 8; ++ni) {
                const int c = cn + warpN * 64 + ni * 8 + lk * 2;
                float v0 = acc[mi][ni][half * 2 + 0] + bias[c];
                float v1 = acc[mi][ni][half * 2 + 1] + bias[c + 1];
                if (flags & FLAG_GELU) {
                    v0 = 0.5f * v0 * (1.0f + erff(v0 * 0.70710678118654752f));
                    v1 = 0.5f * v1 * (1.0f + erff(v1 * 0.70710678118654752f));
                    v0 = rna_f(v0);
                    v1 = rna_f(v1);
                }
                if (flags & FLAG_RES) {
                    float2 r = *(const float2*)&Res[rb + c];
                    v0 += r.x; v1 += r.y;
                }
                float2 o; o.x = v0; o.y = v1;
                *(float2*)&C[rb + c] = o;
            }
        }
    }
}

// ---------------------------------------------------------------------------
// Fourier embed + input projection (rna output: feeds kv GEMM)
// ---------------------------------------------------------------------------
__global__ void embed_kernel(const float* __restrict__ pc,
                             const float* __restrict__ feats,
                             const float* __restrict__ inW,
                             const float* __restrict__ inb,
                             float* __restrict__ out)
{
    __shared__ float e[IN_DIM];
    const int row = blockIdx.x;
    const int t = threadIdx.x;
    if (t < IN_DIM) {
        float v;
        if (t < 3) {
            v = pc[row * 3 + t];
        } else if (t < 27) {
            int j = (t - 3) >> 3, f = (t - 3) & 7;
            v = sinf(pc[row * 3 + j] * (float)(1 << f));
        } else if (t < 51) {
            int j = (t - 27) >> 3, f = (t - 27) & 7;
            v = cosf(pc[row * 3 + j] * (float)(1 << f));
        } else {
            v = feats[row * 3 + (t - 51)];
        }
        e[t] = v;
    }
    __syncthreads();
    #pragma unroll
    for (int rep = 0; rep < 3; ++rep) {
        int o = t + rep * 256;
        const float* w = inW + o * IN_DIM;
        float s = inb[o];
        #pragma unroll
        for (int k = 0; k < IN_DIM; ++k) s = fmaf(w[k], e[k], s);
        out[(long)row * WIDTH + o] = rna_f(s);
    }
}

// ---------------------------------------------------------------------------
// LayerNorm (rna output: feeds qkv / fc GEMMs)
// ---------------------------------------------------------------------------
__global__ void ln_kernel(const float* __restrict__ X,
                          const float* __restrict__ s,
                          const float* __restrict__ b,
                          float* __restrict__ Y)
{
    const int row = blockIdx.x;
    const int t = threadIdx.x;
    const float* x = X + (long)row * WIDTH;
    float v0 = x[t], v1 = x[t + 256], v2 = x[t + 512];
    float sum = v0 + v1 + v2;
    float sq = v0 * v0 + v1 * v1 + v2 * v2;
    __shared__ float red[16];
    #pragma unroll
    for (int o = 16; o; o >>= 1) {
        sum += __shfl_xor_sync(0xffffffffu, sum, o);
        sq  += __shfl_xor_sync(0xffffffffu, sq,  o);
    }
    const int w = t >> 5, l = t & 31;
    if (l == 0) { red[w] = sum; red[w + 8] = sq; }
    __syncthreads();
    if (t < 32) {
        float a = (l < 8) ? red[l] : 0.f;
        float c = (l < 8) ? red[l + 8] : 0.f;
        #pragma unroll
        for (int o = 4; o; o >>= 1) {
            a += __shfl_xor_sync(0xffffffffu, a, o);
            c += __shfl_xor_sync(0xffffffffu, c, o);
        }
        if (l == 0) { red[0] = a; red[1] = c; }
    }
    __syncthreads();
    const float mu = red[0] * (1.f / WIDTH);
    const float var = red[1] * (1.f / WIDTH) - mu * mu;
    const float rs = rsqrtf(var + 1e-5f);
    float* y = Y + (long)row * WIDTH;
    y[t]       = rna_f((v0 - mu) * rs * s[t]       + b[t]);
    y[t + 256] = rna_f((v1 - mu) * rs * s[t + 256] + b[t + 256]);
    y[t + 512] = rna_f((v2 - mu) * rs * s[t + 512] + b[t + 512]);
}

// ---------------------------------------------------------------------------
// Flash attention fp32 SIMT (R8 version — known good; rna output)
// ---------------------------------------------------------------------------
#define FLASH_SMEM ((2 * 128 * 65 + 2 * 64 * 65) * 4)

__global__ __launch_bounds__(256)
void flash_kernel(const float* __restrict__ Qp, const float* __restrict__ Kp,
                  const float* __restrict__ Vp, float* __restrict__ Op,
                  int Lk, int qRS, int kRS, int oRS,
                  long qBS, long kBS, long oBS,
                  int qHS, int kHS, int oHS)
{
    extern __shared__ float sm[];
    float* Qs = sm;
    float* Ps = sm + 128 * 65;
    float* Ks = sm + 2 * 128 * 65;
    float* Vs = Ks + 64 * 65;

    const int tid = threadIdx.x;
    const int tx = tid & 15;
    const int ty = tid >> 4;
    const int qt = blockIdx.x, h = blockIdx.y, b = blockIdx.z;

    const float* Q  = Qp + (long)b * qBS + h * qHS + (long)(qt * 128) * qRS;
    const float* Kb = Kp + (long)b * kBS + h * kHS;
    const float* Vb = Vp + (long)b * kBS + h * kHS;
    float*       O  = Op + (long)b * oBS + h * oHS + (long)(qt * 128) * oRS;

    for (int idx = tid; idx < 128 * 64; idx += 256) {
        int r = idx >> 6, d = idx & 63;
        Qs[r * 65 + d] = Q[(long)r * qRS + d];
    }

    float m[8], l[8], o[8][4];
    #pragma unroll
    for (int i = 0; i < 8; ++i) {
        m[i] = -3.0e38f; l[i] = 0.f;
        #pragma unroll
        for (int j = 0; j < 4; ++j) o[i][j] = 0.f;
    }
    __syncthreads();

    for (int c0 = 0; c0 < Lk; c0 += 64) {
        for (int idx = tid; idx < 64 * 64; idx += 256) {
            int r = idx >> 6, d = idx & 63;
            Ks[r * 65 + d] = Kb[(long)(c0 + r) * kRS + d];
            Vs[r * 65 + d] = Vb[(long)(c0 + r) * kRS + d];
        }
        __syncthreads();

        float s[8][4];
        #pragma unroll
        for (int i = 0; i < 8; ++i)
            #pragma unroll
            for (int j = 0; j < 4; ++j) s[i][j] = 0.f;
        #pragma unroll 16
        for (int d = 0; d < 64; ++d) {
            float a[8], bf[4];
            #pragma unroll
            for (int i = 0; i < 8; ++i) a[i] = Qs[(ty * 8 + i) * 65 + d];
            #pragma unroll
            for (int j = 0; j < 4; ++j) bf[j] = Ks[(tx * 4 + j) * 65 + d];
            #pragma unroll
            for (int i = 0; i < 8; ++i)
                #pragma unroll
                for (int j = 0; j < 4; ++j)
                    s[i][j] = fmaf(a[i], bf[j], s[i][j]);
        }

        #pragma unroll
        for (int i = 0; i < 8; ++i) {
            #pragma unroll
            for (int j = 0; j < 4; ++j) s[i][j] *= 0.125f;
            float mx = fmaxf(fmaxf(s[i][0], s[i][1]), fmaxf(s[i][2], s[i][3]));
            #pragma unroll
            for (int off = 1; off < 16; off <<= 1)
                mx = fmaxf(mx, __shfl_xor_sync(0xffffffffu, mx, off));
            const float mnew = fmaxf(m[i], mx);
            const float corr = __expf(m[i] - mnew);
            m[i] = mnew;
            float rsum = 0.f;
            #pragma unroll
            for (int j = 0; j < 4; ++j) {
                s[i][j] = __expf(s[i][j] - mnew);
                rsum += s[i][j];
            }
            #pragma unroll
            for (int off = 1; off < 16; off <<= 1)
                rsum += __shfl_xor_sync(0xffffffffu, rsum, off);
            l[i] = l[i] * corr + rsum;
            #pragma unroll
            for (int j = 0; j < 4; ++j) {
                o[i][j] *= corr;
                Ps[(ty * 8 + i) * 65 + tx * 4 + j] = s[i][j];
            }
        }
        __syncthreads();

        #pragma unroll 16
        for (int c = 0; c < 64; ++c) {
            float a[8], bf[4];
            #pragma unroll
            for (int i = 0; i < 8; ++i) a[i] = Ps[(ty * 8 + i) * 65 + c];
            #pragma unroll
            for (int j = 0; j < 4; ++j) bf[j] = Vs[c * 65 + tx * 4 + j];
            #pragma unroll
            for (int i = 0; i < 8; ++i)
                #pragma unroll
                for (int j = 0; j < 4; ++j)
                    o[i][j] = fmaf(a[i], bf[j], o[i][j]);
        }
        __syncthreads();
    }

    #pragma unroll
    for (int i = 0; i < 8; ++i) {
        const float inv = 1.f / l[i];
        const int r = ty * 8 + i;
        #pragma unroll
        for (int j = 0; j < 4; ++j)
            O[(long)r * oRS + tx * 4 + j] = rna_f(o[i][j] * inv);
    }
}

__global__ void copy_kernel(const float* __restrict__ src, float* __restrict__ dst, int n)
{
    int i = blockIdx.x * 256 + threadIdx.x;
    if (i < n) dst[i] = src[i];
}

// ---------------------------------------------------------------------------
// kernel_launch
// ---------------------------------------------------------------------------
extern "C" void kernel_launch(void* const* d_in, const int* in_sizes, int n_in,
                              void* d_out, int out_size)
{
    const float* pc       = (const float*)d_in[0];
    const float* feats    = (const float*)d_in[1];
    const float* query    = (const float*)d_in[2];
    const float* in_W     = (const float*)d_in[3];
    const float* in_b     = (const float*)d_in[4];
    const float* ca_qkv_W = (const float*)d_in[5];
    const float* ca_qkv_b = (const float*)d_in[6];
    const float* ca_proj_W= (const float*)d_in[7];
    const float* ca_proj_b= (const float*)d_in[8];
    const float* ln1_s    = (const float*)d_in[9];
    const float* ln1_b    = (const float*)d_in[10];
    const float* qkv_W    = (const float*)d_in[11];
    const float* qkv_b    = (const float*)d_in[12];
    const float* proj_W   = (const float*)d_in[13];
    const float* proj_b   = (const float*)d_in[14];
    const float* ln2_s    = (const float*)d_in[15];
    const float* ln2_b    = (const float*)d_in[16];
    const float* fc_W     = (const float*)d_in[17];
    const float* fc_b     = (const float*)d_in[18];
    const float* fc2_W    = (const float*)d_in[19];
    const float* fc2_b    = (const float*)d_in[20];

    float *data, *kv, *qb, *attn, *x, *h, *ffn, *wtf;
    cudaGetSymbolAddress((void**)&data, g_data);
    cudaGetSymbolAddress((void**)&kv,   g_kv);
    cudaGetSymbolAddress((void**)&qb,   g_q);
    cudaGetSymbolAddress((void**)&attn, g_attn);
    cudaGetSymbolAddress((void**)&x,    g_x);
    cudaGetSymbolAddress((void**)&h,    g_h);
    cudaGetSymbolAddress((void**)&ffn,  g_ffn);
    cudaGetSymbolAddress((void**)&wtf,  g_wtf);

    cudaFuncSetAttribute(flash_kernel, cudaFuncAttributeMaxDynamicSharedMemorySize,
                         FLASH_SMEM);
    cudaFuncSetAttribute(gemm_mma, cudaFuncAttributeMaxDynamicSharedMemorySize,
                         GEMM_SMEM);

    // 0) round all weights to tf32 (single fused launch)
    rna_all<<<(int)((R4_E5 + 255) / 256), 256>>>(
        ca_qkv_W, ca_proj_W, qkv_W, proj_W, fc_W, fc2_W, (float4*)wtf);

    // 1) fourier embed + input projection
    embed_kernel<<<BN_ROWS, 256>>>(pc, feats, in_W, in_b, data);

    // 2) kv = data @ ca_qkv_W[768:2304].T + b[768:]
    gemm_mma<<<dim3((2 * WIDTH) / 128, BN_ROWS / 128), 256, GEMM_SMEM>>>(
        data, wtf + W_CAQKV + (long)WIDTH * WIDTH, ca_qkv_b + WIDTH, nullptr, kv,
        BN_ROWS, 2 * WIDTH, WIDTH, 0);

    // 3) q = query @ ca_qkv_W[:768].T + b[:768]
    gemm_mma<<<dim3(WIDTH / 128, N_LAT / 128), 256, GEMM_SMEM>>>(
        query, wtf + W_CAQKV, ca_qkv_b, nullptr, qb, N_LAT, WIDTH, WIDTH, 0);

    // 4) cross attention (latents attend to 4096 points)
    flash_kernel<<<dim3(N_LAT / 128, HEADS, BATCH), 256, FLASH_SMEM>>>(
        qb, kv, kv + WIDTH, attn,
        NPTS, WIDTH, 2 * WIDTH, WIDTH,
        0L, (long)NPTS * 2 * WIDTH, (long)N_LAT * WIDTH,
        D_HEAD, D_HEAD, D_HEAD);

    // 5) latents = attn @ ca_proj_W.T + b
    gemm_mma<<<dim3(WIDTH / 128, LAT_ROWS / 128), 256, GEMM_SMEM>>>(
        attn, wtf + W_CAPROJ, ca_proj_b, nullptr, x, LAT_ROWS, WIDTH, WIDTH, 0);

    // 6) transformer blocks
    for (int L = 0; L < LAYERS; ++L) {
        ln_kernel<<<LAT_ROWS, 256>>>(x, ln1_s + L * WIDTH, ln1_b + L * WIDTH, h);

        float* qkvb = ffn;
        gemm_mma<<<dim3((3 * WIDTH) / 128, LAT_ROWS / 128), 256, GEMM_SMEM>>>(
            h, wtf + W_QKV + (long)L * 3 * WIDTH * WIDTH, qkv_b + (long)L * 3 * WIDTH,
            nullptr, qkvb, LAT_ROWS, 3 * WIDTH, WIDTH, 0);

        flash_kernel<<<dim3(N_LAT / 128, HEADS, BATCH), 256, FLASH_SMEM>>>(
            qkvb, qkvb + D_HEAD, qkvb + 2 * D_HEAD, attn,
            N_LAT, 3 * WIDTH, 3 * WIDTH, WIDTH,
            (long)N_LAT * 3 * WIDTH, (long)N_LAT * 3 * WIDTH, (long)N_LAT * WIDTH,
            3 * D_HEAD, 3 * D_HEAD, D_HEAD);

        gemm_mma<<<dim3(WIDTH / 128, LAT_ROWS / 128), 256, GEMM_SMEM>>>(
            attn, wtf + W_PROJ + (long)L * WIDTH * WIDTH, proj_b + (long)L * WIDTH,
            x, x, LAT_ROWS, WIDTH, WIDTH, FLAG_RES);

        ln_kernel<<<LAT_ROWS, 256>>>(x, ln2_s + L * WIDTH, ln2_b + L * WIDTH, h);

        gemm_mma<<<dim3((4 * WIDTH) / 128, LAT_ROWS / 128), 256, GEMM_SMEM>>>(
            h, wtf + W_FC + (long)L * 4 * WIDTH * WIDTH, fc_b + (long)L * 4 * WIDTH,
            nullptr, ffn, LAT_ROWS, 4 * WIDTH, WIDTH, FLAG_GELU);

        float* Cout = (L == LAYERS - 1) ? (float*)d_out : x;
        gemm_mma<<<dim3(WIDTH / 128, LAT_ROWS / 128), 256, GEMM_SMEM>>>(
            ffn, wtf + W_FC2 + (long)L * WIDTH * 4 * WIDTH, fc2_b + (long)L * WIDTH,
            x, Cout, LAT_ROWS, WIDTH, 4 * WIDTH, FLAG_RES);
    }

    // 7) pc passthrough if output holds both
    const int lat_elems = LAT_ROWS * WIDTH;
    const int pc_elems = BATCH * NPTS * 3;
    if (out_size >= lat_elems + pc_elems) {
        copy_kernel<<<(pc_elems + 255) / 256, 256>>>(
            pc, (float*)d_out + lat_elems, pc_elems);
    }
}